// round 2
// baseline (speedup 1.0000x reference)
#include <cuda_runtime.h>

// Attend: out = softmax( (q @ k^T) * D^-0.5 + bias, key-mask + causal ) @ v
// q: [B,H,N,D] f32, k/v: [B,N,D] f32 (shared across heads), mask: [B,N] bool,
// bias: [B,H,N,N] f32, out: [B,H,N,D] f32.
// B=4, H=8, N=1024, D=64.

#define BATCH 4
#define HEADS 8
#define NSEQ  1024
#define HDIM  64
#define TI    128   // query rows per block (== threads per block)
#define TJ    32    // key tile

// Additive key-padding mask: 0.0 for valid keys, -1e30 for masked.
__device__ float g_mneg[BATCH * NSEQ];

// The harness may have serialized the jax bool mask as u8, int32, or float32.
// Classify from the first B*N bytes (in-bounds under every candidate encoding):
//   - any byte not in {0,1}            -> float32 (1.0f has bytes 0x80, 0x3F)
//   - some nonzero byte at off%4 != 0  -> u8     (int32 bools have bytes 1..3 == 0)
//   - otherwise                         -> int32
__global__ void mask_conv_kernel(const unsigned char* __restrict__ mraw) {
    __shared__ int s_bad, s_off;
    const int t = threadIdx.x;
    if (t == 0) { s_bad = 0; s_off = 0; }
    __syncthreads();

    int lbad = 0, loff = 0;
    for (int idx = t; idx < BATCH * NSEQ; idx += blockDim.x) {
        unsigned char c = mraw[idx];
        if (c > 1)                  lbad = 1;
        if ((idx & 3) != 0 && c)    loff = 1;
    }
    if (lbad) atomicOr(&s_bad, 1);
    if (loff) atomicOr(&s_off, 1);
    __syncthreads();

    const int cls = s_bad ? 2 : (s_off ? 1 : 0);   // 2=f32, 1=u8, 0=int32
    for (int idx = t; idx < BATCH * NSEQ; idx += blockDim.x) {
        bool valid;
        if (cls == 2)      valid = ((const float*)mraw)[idx] != 0.0f;
        else if (cls == 1) valid = mraw[idx] != 0;
        else               valid = ((const int*)mraw)[idx] != 0;
        g_mneg[idx] = valid ? 0.0f : -1e30f;
    }
}

__global__ __launch_bounds__(TI) void attend_kernel(
    const float* __restrict__ q,
    const float* __restrict__ k,
    const float* __restrict__ v,
    const float* __restrict__ bias,
    float* __restrict__ out)
{
    // Static smem: 8K + 8K + 128*33*4 = 33.3 KB
    __shared__ float Ks[TJ][HDIM];
    __shared__ float Vs[TJ][HDIM];
    __shared__ float Bs[TI][TJ + 1];   // bias tile; reused in-place as score tile

    const int blk = blockIdx.x;
    const int it  = blk % (NSEQ / TI);
    const int h   = (blk / (NSEQ / TI)) % HEADS;
    const int b   =  blk / (NSEQ / TI) / HEADS;
    const int t   = threadIdx.x;
    const int i0  = it * TI;
    const int i   = i0 + t;          // this thread's query row

    const float scale = 0.125f;      // 64^-0.5

    // ---- this thread's q row into registers (16 x LDG.128) ----
    float qr[HDIM];
    {
        const float4* qv = (const float4*)(q + (((long)(b * HEADS + h)) * NSEQ + i) * HDIM);
        #pragma unroll
        for (int c = 0; c < HDIM / 4; c++) {
            float4 u = qv[c];
            qr[4*c+0] = u.x; qr[4*c+1] = u.y; qr[4*c+2] = u.z; qr[4*c+3] = u.w;
        }
    }

    float o[HDIM];
    #pragma unroll
    for (int d = 0; d < HDIM; d++) o[d] = 0.f;
    float m = -1e30f;   // running max (finite sentinel: avoids inf-inf NaNs)
    float l = 0.f;      // running sum of exp

    const float* bias_bh = bias + ((long)(b * HEADS + h)) * NSEQ * NSEQ;
    const float* kb      = k    + (long)b * NSEQ * HDIM;
    const float* vb      = v    + (long)b * NSEQ * HDIM;
    const float* mneg    = g_mneg + b * NSEQ;

    // causal: block needs tiles with j0 <= i0 + TI - 1
    const int ntiles = (i0 + TI) / TJ;

    for (int jt = 0; jt < ntiles; jt++) {
        const int j0 = jt * TJ;

        // ---- cooperative loads: K/V tiles (float4, fully coalesced) ----
        {
            const float4* ksrc = (const float4*)(kb + (long)j0 * HDIM);
            const float4* vsrc = (const float4*)(vb + (long)j0 * HDIM);
            float4* kd = (float4*)&Ks[0][0];
            float4* vd = (float4*)&Vs[0][0];
            #pragma unroll
            for (int c = 0; c < (TJ * HDIM / 4) / TI; c++) {   // 4 iters
                kd[t + c * TI] = ksrc[t + c * TI];
                vd[t + c * TI] = vsrc[t + c * TI];
            }
        }
        // ---- bias tile, coalesced, additive key-padding mask folded in ----
        {
            #pragma unroll
            for (int c = 0; c < TI * TJ / TI; c++) {           // 32 iters
                int e  = c * TI + t;
                int jj = e & (TJ - 1);                         // lanes -> consecutive j: coalesced
                int ii = e >> 5;                               // e / TJ
                Bs[ii][jj] = bias_bh[(long)(i0 + ii) * NSEQ + (j0 + jj)] + mneg[j0 + jj];
            }
        }
        __syncthreads();

        if (j0 <= i) {   // whole tile beyond diagonal for this row -> skip compute
            // ---- phase 1: scores s = q.k*scale + bias, causal mask, tile max ----
            float tmax = -1e30f;
            for (int jj = 0; jj < TJ; jj++) {
                float a0 = 0.f, a1 = 0.f, a2 = 0.f, a3 = 0.f;
                #pragma unroll
                for (int d = 0; d < HDIM; d += 4) {            // Ks reads: warp-uniform -> broadcast
                    a0 += qr[d+0] * Ks[jj][d+0];
                    a1 += qr[d+1] * Ks[jj][d+1];
                    a2 += qr[d+2] * Ks[jj][d+2];
                    a3 += qr[d+3] * Ks[jj][d+3];
                }
                float s = ((a0 + a1) + (a2 + a3)) * scale + Bs[t][jj];
                if (j0 + jj > i) s = -1e30f;                   // causal
                Bs[t][jj] = s;                                 // in-place: bias tile -> score tile
                tmax = fmaxf(tmax, s);
            }

            // ---- phase 2: online softmax update + P @ V ----
            float mt   = fmaxf(m, tmax);
            float corr = __expf(m - mt);
            m = mt;
            l *= corr;
            #pragma unroll
            for (int d = 0; d < HDIM; d++) o[d] *= corr;

            for (int jj = 0; jj < TJ; jj++) {
                float p = __expf(Bs[t][jj] - mt);
                l += p;
                #pragma unroll
                for (int d = 0; d < HDIM; d++)                 // Vs reads: broadcast
                    o[d] += p * Vs[jj][d];
            }
        }
        __syncthreads();
    }

    // ---- epilogue ----
    const float inv = 1.f / l;
    float4* ov = (float4*)(out + (((long)(b * HEADS + h)) * NSEQ + i) * HDIM);
    #pragma unroll
    for (int c = 0; c < HDIM / 4; c++) {
        float4 u;
        u.x = o[4*c+0] * inv; u.y = o[4*c+1] * inv;
        u.z = o[4*c+2] * inv; u.w = o[4*c+3] * inv;
        ov[c] = u;
    }
}

extern "C" void kernel_launch(void* const* d_in, const int* in_sizes, int n_in,
                              void* d_out, int out_size) {
    const float* q    = (const float*)d_in[0];                  // [4,8,1024,64]
    const float* k    = (const float*)d_in[1];                  // [4,1024,64]
    const float* v    = (const float*)d_in[2];                  // [4,1024,64]
    const unsigned char* mask = (const unsigned char*)d_in[3];  // [4,1024] bool (dtype probed)
    const float* bias = (const float*)d_in[4];                  // [4,8,1024,1024]
    float*       out  = (float*)d_out;                          // [4,8,1024,64]

    mask_conv_kernel<<<1, 256>>>(mask);

    dim3 grid(BATCH * HEADS * (NSEQ / TI));   // 256 blocks
    dim3 block(TI);                           // 128 threads
    attend_kernel<<<grid, block>>>(q, k, v, bias, out);
}

// round 5
// speedup vs baseline: 1.2126x; 1.2126x over previous
#include <cuda_runtime.h>

// Attend: out = softmax( (q @ k^T) * D^-0.5 + bias, key-mask + causal ) @ v
// q: [B,H,N,D] f32, k/v: [B,N,D] f32 (shared across heads), mask: [B,N] bool,
// bias: [B,H,N,N] f32, out: [B,H,N,D] f32.  B=4, H=8, N=1024, D=64.

#define BATCH 4
#define HEADS 8
#define NSEQ  1024
#define HDIM  64
#define TI    64    // query rows per block
#define TJ    32    // key tile
#define DH    32    // d-half owned by one thread
#define NT    128   // threads: 64 rows x 2 d-halves

typedef unsigned long long u64;

// ---- packed f32x2 helpers (sm_10x: FFMA2 only reachable via PTX) ----
__device__ __forceinline__ u64 ffma2(u64 a, u64 b, u64 c) {
    u64 d; asm("fma.rn.f32x2 %0, %1, %2, %3;" : "=l"(d) : "l"(a), "l"(b), "l"(c)); return d;
}
__device__ __forceinline__ u64 fmul2(u64 a, u64 b) {
    u64 d; asm("mul.rn.f32x2 %0, %1, %2;" : "=l"(d) : "l"(a), "l"(b)); return d;
}
__device__ __forceinline__ u64 pack2(float lo, float hi) {
    u64 u; asm("mov.b64 %0, {%1, %2};" : "=l"(u) : "f"(lo), "f"(hi)); return u;
}
__device__ __forceinline__ void unpack2(u64 u, float& lo, float& hi) {
    asm("mov.b64 {%0, %1}, %2;" : "=f"(lo), "=f"(hi) : "l"(u));
}

// Additive key-padding mask: 0.0 for valid keys, -1e30 for masked.
__device__ float g_mneg[BATCH * NSEQ];

// Dtype-probing mask decode (validated in R2):
//   any byte not in {0,1}            -> float32
//   nonzero byte at off%4 != 0       -> u8
//   otherwise                         -> int32
__global__ void mask_conv_kernel(const unsigned char* __restrict__ mraw) {
    __shared__ int s_bad, s_off;
    const int t = threadIdx.x;
    if (t == 0) { s_bad = 0; s_off = 0; }
    __syncthreads();
    int lbad = 0, loff = 0;
    for (int idx = t; idx < BATCH * NSEQ; idx += blockDim.x) {
        unsigned char c = mraw[idx];
        if (c > 1)               lbad = 1;
        if ((idx & 3) != 0 && c) loff = 1;
    }
    if (lbad) atomicOr(&s_bad, 1);
    if (loff) atomicOr(&s_off, 1);
    __syncthreads();
    const int cls = s_bad ? 2 : (s_off ? 1 : 0);
    for (int idx = t; idx < BATCH * NSEQ; idx += blockDim.x) {
        bool valid;
        if (cls == 2)      valid = ((const float*)mraw)[idx] != 0.0f;
        else if (cls == 1) valid = mraw[idx] != 0;
        else               valid = ((const int*)mraw)[idx] != 0;
        g_mneg[idx] = valid ? 0.0f : -1e30f;
    }
}

__global__ __launch_bounds__(NT, 4) void attend_kernel(
    const float* __restrict__ q,
    const float* __restrict__ k,
    const float* __restrict__ v,
    const float* __restrict__ bias,
    float* __restrict__ out)
{
    // Static smem: 8K + 8K + 64*33*4 (8.25K) + 64*66*4 (16.5K) = 40.8 KB
    __shared__ float Ks[TJ][HDIM];
    __shared__ float Vs[TJ][HDIM];
    __shared__ float Bs[TI][TJ + 1];    // bias(+mask) tile
    __shared__ float Ph[TI][2 * TJ + 2]; // partial dots [r][2*jj+hd], stride 66

    const int blk = blockIdx.x;
    const int it  = 15 - (blk & 15);    // heavy (high-i) blocks launch first
    const int h   = (blk >> 4) & 7;
    const int b   =  blk >> 7;
    const int t   = threadIdx.x;
    const int r   = t & (TI - 1);       // query row within tile
    const int hd  = t >> 6;             // d-half: 0 or 1 (warp-uniform)
    const int i0  = it * TI;
    const int i   = i0 + r;

    const float scale = 0.125f;         // 64^-0.5

    // ---- this thread's q half-row into packed registers (8 x LDG.128) ----
    u64 q2[DH / 2];
    {
        const ulonglong2* qsrc = (const ulonglong2*)(q + (((long)(b * HEADS + h)) * NSEQ + i) * HDIM + hd * DH);
        #pragma unroll
        for (int x = 0; x < DH / 4; x++) { ulonglong2 u = qsrc[x]; q2[2*x] = u.x; q2[2*x+1] = u.y; }
    }

    u64 o2[DH / 2];
    #pragma unroll
    for (int x = 0; x < DH / 2; x++) o2[x] = 0ull;   // two packed 0.0f
    float m = -1e30f;   // running max (finite sentinel: no inf-inf NaNs)
    float l = 0.f;      // running sum of exp

    const float* bias_bh = bias + ((long)(b * HEADS + h)) * NSEQ * NSEQ;
    const float* kb      = k    + (long)b * NSEQ * HDIM;
    const float* vb      = v    + (long)b * NSEQ * HDIM;
    const float* mneg    = g_mneg + b * NSEQ;

    const int ntiles = (i0 + TI) / TJ;  // causal: only tiles with j0 <= i0+TI-1

    for (int jt = 0; jt < ntiles; jt++) {
        const int j0 = jt * TJ;

        // ---- cooperative loads: K/V tiles (float4, coalesced: 4 each) ----
        {
            const float4* ksrc = (const float4*)(kb + (long)j0 * HDIM);
            const float4* vsrc = (const float4*)(vb + (long)j0 * HDIM);
            float4* kd = (float4*)&Ks[0][0];
            float4* vd = (float4*)&Vs[0][0];
            #pragma unroll
            for (int c = 0; c < 4; c++) {
                kd[t + c * NT] = ksrc[t + c * NT];
                vd[t + c * NT] = vsrc[t + c * NT];
            }
        }
        // ---- bias tile, coalesced, additive key mask folded in (16 each) ----
        #pragma unroll
        for (int c = 0; c < 16; c++) {
            int e  = c * NT + t;
            int jj = e & (TJ - 1);
            int ii = e >> 5;
            Bs[ii][jj] = bias_bh[(long)(i0 + ii) * NSEQ + (j0 + jj)] + mneg[j0 + jj];
        }
        __syncthreads();

        // ---- phase 1: partial dot over this thread's d-half ----
        if (j0 <= i) {
            for (int jj = 0; jj < TJ; jj++) {
                u64 a0 = 0ull, a1 = 0ull, a2 = 0ull, a3 = 0ull;
                const ulonglong2* kr = (const ulonglong2*)&Ks[jj][hd * DH];  // broadcast reads
                #pragma unroll
                for (int x = 0; x < DH / 8; x++) {   // 4 iters: 8 LDS.128, 16 FFMA2
                    ulonglong2 k01 = kr[2*x];
                    ulonglong2 k23 = kr[2*x + 1];
                    a0 = ffma2(q2[4*x + 0], k01.x, a0);
                    a1 = ffma2(q2[4*x + 1], k01.y, a1);
                    a2 = ffma2(q2[4*x + 2], k23.x, a2);
                    a3 = ffma2(q2[4*x + 3], k23.y, a3);
                }
                float x0, x1, x2, x3, x4, x5, x6, x7;
                unpack2(a0, x0, x1); unpack2(a1, x2, x3);
                unpack2(a2, x4, x5); unpack2(a3, x6, x7);
                Ph[r][2 * jj + hd] = ((x0 + x1) + (x2 + x3)) + ((x4 + x5) + (x6 + x7));
            }
        }
        __syncthreads();

        // ---- phase 2: full scores, online softmax, P @ V (packed) ----
        if (j0 <= i) {
            // pass A: tile max (Ph/Bs read-only -> no extra sync needed)
            float tmax = -1e30f;
            for (int jj = 0; jj < TJ; jj++) {
                float2 ph = *(const float2*)&Ph[r][2 * jj];
                float s = (ph.x + ph.y) * scale + Bs[r][jj];
                if (j0 + jj > i) s = -1e30f;            // causal
                tmax = fmaxf(tmax, s);
            }
            float mt   = fmaxf(m, tmax);
            float corr = __expf(m - mt);
            m = mt;
            l *= corr;
            u64 c2 = pack2(corr, corr);
            #pragma unroll
            for (int x = 0; x < DH / 2; x++) o2[x] = fmul2(o2[x], c2);

            // pass B: recompute s (cheaper than storing; avoids write races)
            for (int jj = 0; jj < TJ; jj++) {
                float2 ph = *(const float2*)&Ph[r][2 * jj];
                float s = (ph.x + ph.y) * scale + Bs[r][jj];
                if (j0 + jj > i) s = -1e30f;
                float p = __expf(s - mt);
                l += p;
                u64 p2 = pack2(p, p);
                const ulonglong2* vr = (const ulonglong2*)&Vs[jj][hd * DH];  // broadcast
                #pragma unroll
                for (int x = 0; x < DH / 4; x++) {      // 8 LDS.128, 16 FFMA2
                    ulonglong2 vv = vr[x];
                    o2[2*x]     = ffma2(p2, vv.x, o2[2*x]);
                    o2[2*x + 1] = ffma2(p2, vv.y, o2[2*x + 1]);
                }
            }
        }
        __syncthreads();   // protect Ks/Vs/Bs/Ph before next tile's loads
    }

    // ---- epilogue: this thread writes its own 32 output floats ----
    const float inv = 1.f / l;     // l identical in both hd threads of a row
    u64 inv2 = pack2(inv, inv);
    ulonglong2* od = (ulonglong2*)(out + (((long)(b * HEADS + h)) * NSEQ + i) * HDIM + hd * DH);
    #pragma unroll
    for (int x = 0; x < DH / 4; x++) {
        ulonglong2 u;
        u.x = fmul2(o2[2*x],     inv2);
        u.y = fmul2(o2[2*x + 1], inv2);
        od[x] = u;
    }
}

extern "C" void kernel_launch(void* const* d_in, const int* in_sizes, int n_in,
                              void* d_out, int out_size) {
    const float* q    = (const float*)d_in[0];                  // [4,8,1024,64]
    const float* k    = (const float*)d_in[1];                  // [4,1024,64]
    const float* v    = (const float*)d_in[2];                  // [4,1024,64]
    const unsigned char* mask = (const unsigned char*)d_in[3];  // [4,1024] bool (dtype probed)
    const float* bias = (const float*)d_in[4];                  // [4,8,1024,1024]
    float*       out  = (float*)d_out;                          // [4,8,1024,64]

    mask_conv_kernel<<<1, 256>>>(mask);

    dim3 grid(BATCH * HEADS * (NSEQ / TI));   // 512 blocks
    dim3 block(NT);                           // 128 threads
    attend_kernel<<<grid, block>>>(q, k, v, bias, out);
}